// round 1
// baseline (speedup 1.0000x reference)
#include <cuda_runtime.h>
#include <cstdint>

// ---------------------------------------------------------------------------
// CausalSelfAttention: y = proj( softmax_causal( (xWq)(xWk)^T / sqrt(64) ) (xWv) )
// B=4, T=2048, C=768, H=12, Dh=64
// Stage 1: qkv = x @ w_attn + b_attn          [8192, 2304]   (SGEMM)
// Stage 2: flash attention per (b,h,qtile)    -> y [8192, 768]
// Stage 3: out = y @ w_proj + b_proj          [8192, 768]    (SGEMM)
// ---------------------------------------------------------------------------

#define B_ 4
#define T_ 2048
#define C_ 768
#define H_ 12
#define DH_ 64
#define ROWS_ (B_ * T_)       // 8192
#define QKVC_ (3 * C_)        // 2304

// Scratch (no cudaMalloc allowed) ------------------------------------------
__device__ float g_qkv[ROWS_ * QKVC_];   // ~75.5 MB
__device__ float g_y[ROWS_ * C_];        // ~25.2 MB

// ---------------------------------------------------------------------------
// SGEMM: C[M,N] = A[M,K] @ B[K,N] + bias[N]
// A,B,C row-major. M%128==0, N%128==0, K%8==0 guaranteed by problem shapes.
// 128x128 block tile, BK=8, 256 threads, 8x8 per-thread register tile.
// ---------------------------------------------------------------------------
__global__ __launch_bounds__(256, 2)
void sgemm_bias_kernel(const float* __restrict__ A, const float* __restrict__ Bm,
                       const float* __restrict__ bias, float* __restrict__ Cm,
                       int M, int N, int K)
{
    __shared__ float As[8][132];   // padded: conflict-free transposed stores
    __shared__ float Bs[8][128];

    const int tid = threadIdx.x;
    const int tx = tid & 15;        // 0..15  (col group)
    const int ty = tid >> 4;        // 0..15  (row group)
    const int rowBase = blockIdx.y * 128;
    const int colBase = blockIdx.x * 128;

    const int arow = tid >> 1;          // 0..127
    const int acol = (tid & 1) * 4;     // 0 or 4
    const int brow = tid >> 5;          // 0..7
    const int bcol = (tid & 31) * 4;    // 0..124

    float acc[8][8];
#pragma unroll
    for (int i = 0; i < 8; i++)
#pragma unroll
        for (int j = 0; j < 8; j++) acc[i][j] = 0.f;

    for (int k0 = 0; k0 < K; k0 += 8) {
        // prefetch into registers while previous tile still being consumed
        float4 av = *(const float4*)(A + (size_t)(rowBase + arow) * K + k0 + acol);
        float4 bv = *(const float4*)(Bm + (size_t)(k0 + brow) * N + colBase + bcol);
        __syncthreads();
        As[acol + 0][arow] = av.x;
        As[acol + 1][arow] = av.y;
        As[acol + 2][arow] = av.z;
        As[acol + 3][arow] = av.w;
        *(float4*)&Bs[brow][bcol] = bv;
        __syncthreads();
#pragma unroll
        for (int k = 0; k < 8; k++) {
            float a[8], b[8];
            float4 b0 = *(const float4*)&Bs[k][tx * 8];
            float4 b1 = *(const float4*)&Bs[k][tx * 8 + 4];
            b[0] = b0.x; b[1] = b0.y; b[2] = b0.z; b[3] = b0.w;
            b[4] = b1.x; b[5] = b1.y; b[6] = b1.z; b[7] = b1.w;
#pragma unroll
            for (int i = 0; i < 8; i++) a[i] = As[k][ty * 8 + i];
#pragma unroll
            for (int i = 0; i < 8; i++)
#pragma unroll
                for (int j = 0; j < 8; j++)
                    acc[i][j] += a[i] * b[j];
        }
    }

#pragma unroll
    for (int i = 0; i < 8; i++) {
        const int r = rowBase + ty * 8 + i;
#pragma unroll
        for (int j = 0; j < 8; j += 4) {
            const int c = colBase + tx * 8 + j;
            float4 o;
            o.x = acc[i][j + 0] + bias[c + 0];
            o.y = acc[i][j + 1] + bias[c + 1];
            o.z = acc[i][j + 2] + bias[c + 2];
            o.w = acc[i][j + 3] + bias[c + 3];
            *(float4*)(Cm + (size_t)r * N + c) = o;
        }
    }
}

// ---------------------------------------------------------------------------
// Flash attention, fp32 SIMT.
// grid = (T/64, B*H); 256 threads; 64x64 Q/K tiles, Dh=64.
// Thread (tx,ty) owns a 4x4 micro-tile: rows ty*4.., cols tx*4..
// smem: Qs[64][64] + Kt[64][64] (K transposed [d][j], reused as P[i][j])
//       + Vs[64][64]  == exactly 48 KB static.
// ---------------------------------------------------------------------------
__global__ __launch_bounds__(256)
void attn_kernel(const float* __restrict__ qkv, float* __restrict__ y)
{
    __shared__ float Qs[64 * 64];
    __shared__ float Kt[64 * 64];   // K^T during S; P during PV
    __shared__ float Vs[64 * 64];

    const int qt = blockIdx.x;              // query tile 0..31
    const int bh = blockIdx.y;              // 0..47
    const int b = bh / H_;
    const int h = bh % H_;
    const int tid = threadIdx.x;
    const int tx = tid & 15;
    const int ty = tid >> 4;

    const size_t rowStride = QKVC_;
    const float* base = qkv + (size_t)b * T_ * rowStride + h * DH_;
    const int qBase = qt * 64;

    // load Q tile (coalesced float4)
    for (int idx = tid; idx < 64 * 16; idx += 256) {
        const int r = idx >> 4;
        const int c4 = (idx & 15) << 2;
        float4 v = *(const float4*)(base + (size_t)(qBase + r) * rowStride + c4);
        *(float4*)&Qs[r * 64 + c4] = v;
    }

    float m_i[4], l_i[4], o[4][4];
#pragma unroll
    for (int i = 0; i < 4; i++) {
        m_i[i] = -1e30f; l_i[i] = 0.f;
#pragma unroll
        for (int d = 0; d < 4; d++) o[i][d] = 0.f;
    }

    for (int kt = 0; kt <= qt; kt++) {
        const int kBase = kt * 64;
        __syncthreads();   // Q ready (iter 0) / previous PV-GEMM done with Kt,Vs
        // load K transposed + V direct
        for (int idx = tid; idx < 64 * 16; idx += 256) {
            const int r = idx >> 4;
            const int c4 = (idx & 15) << 2;
            const float* kp = base + C_ + (size_t)(kBase + r) * rowStride + c4;
            float4 kv = *(const float4*)kp;
            Kt[(c4 + 0) * 64 + r] = kv.x;
            Kt[(c4 + 1) * 64 + r] = kv.y;
            Kt[(c4 + 2) * 64 + r] = kv.z;
            Kt[(c4 + 3) * 64 + r] = kv.w;
            float4 vv = *(const float4*)(base + 2 * C_ + (size_t)(kBase + r) * rowStride + c4);
            *(float4*)&Vs[r * 64 + c4] = vv;
        }
        __syncthreads();

        // S = Q @ K^T (4x4 per thread)
        float s[4][4];
#pragma unroll
        for (int i = 0; i < 4; i++)
#pragma unroll
            for (int j = 0; j < 4; j++) s[i][j] = 0.f;

#pragma unroll 4
        for (int dk = 0; dk < 64; dk++) {
            float a[4];
#pragma unroll
            for (int i = 0; i < 4; i++) a[i] = Qs[(ty * 4 + i) * 64 + dk];
            float4 bb = *(const float4*)&Kt[dk * 64 + tx * 4];
#pragma unroll
            for (int i = 0; i < 4; i++) {
                s[i][0] += a[i] * bb.x;
                s[i][1] += a[i] * bb.y;
                s[i][2] += a[i] * bb.z;
                s[i][3] += a[i] * bb.w;
            }
        }

        const float scale = 0.125f;   // 1/sqrt(64)
        const bool diag = (kt == qt);
#pragma unroll
        for (int i = 0; i < 4; i++) {
#pragma unroll
            for (int j = 0; j < 4; j++) {
                float v = s[i][j] * scale;
                if (diag && (tx * 4 + j) > (ty * 4 + i)) v = -1e30f;
                s[i][j] = v;
            }
            // row max across the 16-lane row group
            float mloc = fmaxf(fmaxf(s[i][0], s[i][1]), fmaxf(s[i][2], s[i][3]));
#pragma unroll
            for (int off = 8; off >= 1; off >>= 1)
                mloc = fmaxf(mloc, __shfl_xor_sync(0xffffffffu, mloc, off));
            const float mnew = fmaxf(m_i[i], mloc);
            const float alpha = __expf(m_i[i] - mnew);
            float lloc = 0.f;
#pragma unroll
            for (int j = 0; j < 4; j++) {
                s[i][j] = __expf(s[i][j] - mnew);
                lloc += s[i][j];
            }
#pragma unroll
            for (int off = 8; off >= 1; off >>= 1)
                lloc += __shfl_xor_sync(0xffffffffu, lloc, off);
            l_i[i] = l_i[i] * alpha + lloc;
            m_i[i] = mnew;
#pragma unroll
            for (int d = 0; d < 4; d++) o[i][d] *= alpha;
        }

        __syncthreads();   // all threads done reading Kt for S
        // write P into Kt region (row-major [i][j]) — contiguous float4
#pragma unroll
        for (int i = 0; i < 4; i++) {
            float4 p4 = make_float4(s[i][0], s[i][1], s[i][2], s[i][3]);
            *(float4*)&Kt[(ty * 4 + i) * 64 + tx * 4] = p4;
        }
        __syncthreads();

        // O += P @ V
#pragma unroll 4
        for (int j = 0; j < 64; j++) {
            float a[4];
#pragma unroll
            for (int i = 0; i < 4; i++) a[i] = Kt[(ty * 4 + i) * 64 + j];
            float4 vv = *(const float4*)&Vs[j * 64 + tx * 4];
#pragma unroll
            for (int i = 0; i < 4; i++) {
                o[i][0] += a[i] * vv.x;
                o[i][1] += a[i] * vv.y;
                o[i][2] += a[i] * vv.z;
                o[i][3] += a[i] * vv.w;
            }
        }
    }

    // y[(b*T + q)*C + h*64 + d] = O / l
#pragma unroll
    for (int i = 0; i < 4; i++) {
        const float inv = 1.0f / l_i[i];
        const int q = qBase + ty * 4 + i;
        float4 r4 = make_float4(o[i][0] * inv, o[i][1] * inv, o[i][2] * inv, o[i][3] * inv);
        *(float4*)(y + ((size_t)b * T_ + q) * C_ + h * DH_ + tx * 4) = r4;
    }
}

// ---------------------------------------------------------------------------
extern "C" void kernel_launch(void* const* d_in, const int* in_sizes, int n_in,
                              void* d_out, int out_size)
{
    const float* x      = (const float*)d_in[0];
    const float* w_attn = (const float*)d_in[1];
    const float* b_attn = (const float*)d_in[2];
    const float* w_proj = (const float*)d_in[3];
    const float* b_proj = (const float*)d_in[4];
    float* out = (float*)d_out;

    float* qkv = nullptr;
    float* y   = nullptr;
    cudaGetSymbolAddress((void**)&qkv, g_qkv);
    cudaGetSymbolAddress((void**)&y,   g_y);

    // Stage 1: qkv = x @ w_attn + b_attn      [8192 x 2304]
    {
        dim3 grid(QKVC_ / 128, ROWS_ / 128);
        sgemm_bias_kernel<<<grid, 256>>>(x, w_attn, b_attn, qkv, ROWS_, QKVC_, C_);
    }
    // Stage 2: flash attention -> y           [8192 x 768]
    {
        dim3 grid(T_ / 64, B_ * H_);
        attn_kernel<<<grid, 256>>>(qkv, y);
    }
    // Stage 3: out = y @ w_proj + b_proj      [8192 x 768]
    {
        dim3 grid(C_ / 128, ROWS_ / 128);
        sgemm_bias_kernel<<<grid, 256>>>(y, w_proj, b_proj, out, ROWS_, C_, C_);
    }
}

// round 4
// speedup vs baseline: 2.4155x; 2.4155x over previous
#include <cuda_runtime.h>
#include <cuda_bf16.h>
#include <cstdint>

// ---------------------------------------------------------------------------
// CausalSelfAttention on GB300 (sm_103 family target — no 'a' features).
// All matmuls on tensor pipe via mma.sync.m16n8k16 bf16 with hi/lo splitting.
// Stage 1: qkv = x @ w_attn + b_attn      (bf16-split mma GEMM, fp32 out)
// Stage 2: causal flash attention         (bf16-split mma, fp32 softmax)
// Stage 3: out = y @ w_proj + b_proj      (bf16-split mma GEMM)
// ---------------------------------------------------------------------------

#define B_ 4
#define T_ 2048
#define C_ 768
#define H_ 12
#define ROWS_ 8192
#define QKVC_ 2304

// ---------------- scratch ---------------------------------------------------
__device__ __align__(256) float          g_qkv[ROWS_ * QKVC_];
__device__ __align__(256) __nv_bfloat16  g_xhi[ROWS_ * C_];
__device__ __align__(256) __nv_bfloat16  g_xlo[ROWS_ * C_];
__device__ __align__(256) __nv_bfloat16  g_yhi[ROWS_ * C_];
__device__ __align__(256) __nv_bfloat16  g_ylo[ROWS_ * C_];
__device__ __align__(256) __nv_bfloat16  g_wa_hi[QKVC_ * C_];  // w_attn^T [N,K]
__device__ __align__(256) __nv_bfloat16  g_wa_lo[QKVC_ * C_];
__device__ __align__(256) __nv_bfloat16  g_wp_hi[C_ * C_];     // w_proj^T [N,K]
__device__ __align__(256) __nv_bfloat16  g_wp_lo[C_ * C_];

// ---------------- helpers ---------------------------------------------------
__device__ __forceinline__ uint32_t smem_u32(const void* p) {
    uint32_t a;
    asm("{ .reg .u64 t; cvta.to.shared.u64 t, %1; cvt.u32.u64 %0, t; }"
        : "=r"(a) : "l"(p));
    return a;
}
#define SWZ(x) ((x) ^ (((x) >> 3) & 0x70))

__device__ __forceinline__ void cpa16(uint32_t dst, const void* src) {
    asm volatile("cp.async.cg.shared.global [%0], [%1], 16;" :: "r"(dst), "l"(src));
}
__device__ __forceinline__ void cpa_commit() { asm volatile("cp.async.commit_group;"); }

__device__ __forceinline__ void ldsm_x4(uint32_t& r0, uint32_t& r1, uint32_t& r2,
                                        uint32_t& r3, uint32_t addr) {
    asm volatile("ldmatrix.sync.aligned.m8n8.x4.shared.b16 {%0,%1,%2,%3}, [%4];"
                 : "=r"(r0), "=r"(r1), "=r"(r2), "=r"(r3) : "r"(addr));
}
__device__ __forceinline__ void ldsm_x2(uint32_t& r0, uint32_t& r1, uint32_t addr) {
    asm volatile("ldmatrix.sync.aligned.m8n8.x2.shared.b16 {%0,%1}, [%2];"
                 : "=r"(r0), "=r"(r1) : "r"(addr));
}
__device__ __forceinline__ void ldsm_x2t(uint32_t& r0, uint32_t& r1, uint32_t addr) {
    asm volatile("ldmatrix.sync.aligned.m8n8.x2.trans.shared.b16 {%0,%1}, [%2];"
                 : "=r"(r0), "=r"(r1) : "r"(addr));
}
__device__ __forceinline__ void mma_bf16(float* c, const uint32_t* a,
                                         uint32_t b0, uint32_t b1) {
    asm volatile("mma.sync.aligned.m16n8k16.row.col.f32.bf16.bf16.f32 "
                 "{%0,%1,%2,%3}, {%4,%5,%6,%7}, {%8,%9}, {%0,%1,%2,%3};"
                 : "+f"(c[0]), "+f"(c[1]), "+f"(c[2]), "+f"(c[3])
                 : "r"(a[0]), "r"(a[1]), "r"(a[2]), "r"(a[3]), "r"(b0), "r"(b1));
}

// split fp32 pair -> packed bf16x2 (hi) + packed bf16x2 (residual lo)
__device__ __forceinline__ void split2(float a, float b, uint32_t& h, uint32_t& l) {
    __nv_bfloat16 ha = __float2bfloat16(a), hb = __float2bfloat16(b);
    __nv_bfloat16 la = __float2bfloat16(a - __bfloat162float(ha));
    __nv_bfloat16 lb = __float2bfloat16(b - __bfloat162float(hb));
    __nv_bfloat162 hh(ha, hb), ll(la, lb);
    h = *(uint32_t*)&hh;
    l = *(uint32_t*)&ll;
}

// ---------------------------------------------------------------------------
// Conversion kernels
// ---------------------------------------------------------------------------
__global__ void split_rows_kernel(const float* __restrict__ in,
                                  __nv_bfloat16* __restrict__ hi,
                                  __nv_bfloat16* __restrict__ lo, int n4)
{
    int i = blockIdx.x * blockDim.x + threadIdx.x;
    if (i >= n4) return;
    float4 v = ((const float4*)in)[i];
    uint32_t h0, l0, h1, l1;
    split2(v.x, v.y, h0, l0);
    split2(v.z, v.w, h1, l1);
    uint32_t* hp = (uint32_t*)(hi + 4 * (size_t)i);
    uint32_t* lp = (uint32_t*)(lo + 4 * (size_t)i);
    hp[0] = h0; hp[1] = h1;
    lp[0] = l0; lp[1] = l1;
}

// w [K,N] fp32 -> hiT/loT [N,K] bf16
__global__ void split_transpose_kernel(const float* __restrict__ w,
                                       __nv_bfloat16* __restrict__ hiT,
                                       __nv_bfloat16* __restrict__ loT, int K, int N)
{
    __shared__ float t[32][33];
    const int n0 = blockIdx.x * 32, k0 = blockIdx.y * 32;
    const int tx = threadIdx.x, ty = threadIdx.y;   // 32 x 8
#pragma unroll
    for (int j = 0; j < 4; j++)
        t[ty + j * 8][tx] = w[(size_t)(k0 + ty + j * 8) * N + n0 + tx];
    __syncthreads();
#pragma unroll
    for (int j = 0; j < 4; j++) {
        const int n = ty + j * 8;
        float v = t[tx][n];
        __nv_bfloat16 h = __float2bfloat16(v);
        __nv_bfloat16 l = __float2bfloat16(v - __bfloat162float(h));
        hiT[(size_t)(n0 + n) * K + k0 + tx] = h;
        loT[(size_t)(n0 + n) * K + k0 + tx] = l;
    }
}

// ---------------------------------------------------------------------------
// GEMM: C[M,N] = (Ahi+Alo)[M,K] @ (Bhi+Blo)[N,K]^T + bias   (fp32 out)
// 128x128 tile, BK=64, 8 warps (2m x 4n), 3-stage cp.async, SW128 smem.
// ---------------------------------------------------------------------------
#define G_STAGE 65536   // Ahi 16K | Alo 16K | Bhi 16K | Blo 16K
#define G_SMEM  (3 * G_STAGE)

__device__ __forceinline__ void gemm_load_chunk(
    uint32_t sb, const __nv_bfloat16* Ahi, const __nv_bfloat16* Alo,
    const __nv_bfloat16* Bhi, const __nv_bfloat16* Blo,
    int rowBase, int colBase, int K, int kc, int stage, int tid)
{
    const uint32_t base = sb + stage * G_STAGE;
    const int k0 = kc * 64;
    const __nv_bfloat16* srcs[4] = { Ahi, Alo, Bhi, Blo };
#pragma unroll
    for (int t = 0; t < 4; t++) {
        const __nv_bfloat16* src = srcs[t];
        const int gb = (t < 2) ? rowBase : colBase;
        const uint32_t soff = base + t * 16384;
#pragma unroll
        for (int i = 0; i < 4; i++) {
            const int seg = tid + i * 256;
            const int r = seg >> 3, g = seg & 7;
            cpa16(soff + SWZ(r * 128 + g * 16),
                  src + (size_t)(gb + r) * K + k0 + g * 8);
        }
    }
    cpa_commit();
}

__global__ __launch_bounds__(256, 1)
void gemm_mma_kernel(const __nv_bfloat16* __restrict__ Ahi, const __nv_bfloat16* __restrict__ Alo,
                     const __nv_bfloat16* __restrict__ Bhi, const __nv_bfloat16* __restrict__ Blo,
                     const float* __restrict__ bias, float* __restrict__ Cm,
                     int M, int N, int K)
{
    extern __shared__ char smem[];
    const uint32_t sb = smem_u32(smem);
    const int tid = threadIdx.x, wid = tid >> 5, lane = tid & 31;
    const int wm = wid >> 2, wn = wid & 3;          // warp tile 64m x 32n
    const int rowBase = blockIdx.y * 128, colBase = blockIdx.x * 128;
    const int NK = K / 64;

    float c[4][4][4];
#pragma unroll
    for (int i = 0; i < 4; i++)
#pragma unroll
        for (int j = 0; j < 4; j++)
#pragma unroll
            for (int k = 0; k < 4; k++) c[i][j][k] = 0.f;

    gemm_load_chunk(sb, Ahi, Alo, Bhi, Blo, rowBase, colBase, K, 0, 0, tid);
    gemm_load_chunk(sb, Ahi, Alo, Bhi, Blo, rowBase, colBase, K, 1, 1, tid);
    gemm_load_chunk(sb, Ahi, Alo, Bhi, Blo, rowBase, colBase, K, 2, 2, tid);

    // precomputed lane fragments of addresses
    const int aRow = wm * 64 + (lane & 15);
    const uint32_t aSegOff = ((lane >> 4) & 1) * 16;
    const int bRowL = wn * 32 + (lane & 7);
    const uint32_t bSegOff = ((lane >> 3) & 1) * 16;

    for (int kc = 0; kc < NK; kc++) {
        asm volatile("cp.async.wait_group 2;" ::: "memory");
        __syncthreads();
        const uint32_t st = sb + (kc % 3) * G_STAGE;
#pragma unroll
        for (int ks = 0; ks < 4; ks++) {
            uint32_t bh[4][2], bl[4][2];
#pragma unroll
            for (int nj = 0; nj < 4; nj++) {
                const uint32_t boff = SWZ((uint32_t)(bRowL + nj * 8) * 128 + ks * 32 + bSegOff);
                ldsm_x2(bh[nj][0], bh[nj][1], st + 32768 + boff);
                ldsm_x2(bl[nj][0], bl[nj][1], st + 49152 + boff);
            }
#pragma unroll
            for (int mi = 0; mi < 4; mi++) {
                uint32_t ah[4], al[4];
                const uint32_t aoff = SWZ((uint32_t)(aRow + mi * 16) * 128 + ks * 32 + aSegOff);
                ldsm_x4(ah[0], ah[1], ah[2], ah[3], st + aoff);
                ldsm_x4(al[0], al[1], al[2], al[3], st + 16384 + aoff);
#pragma unroll
                for (int nj = 0; nj < 4; nj++) {
                    mma_bf16(c[mi][nj], ah, bh[nj][0], bh[nj][1]);
                    mma_bf16(c[mi][nj], al, bh[nj][0], bh[nj][1]);
                    mma_bf16(c[mi][nj], ah, bl[nj][0], bl[nj][1]);
                }
            }
        }
        __syncthreads();
        if (kc + 3 < NK)
            gemm_load_chunk(sb, Ahi, Alo, Bhi, Blo, rowBase, colBase, K,
                            kc + 3, kc % 3, tid);
    }

    // epilogue
    const int g = lane >> 2, q2 = (lane & 3) * 2;
#pragma unroll
    for (int mi = 0; mi < 4; mi++) {
        const int row0 = rowBase + wm * 64 + mi * 16 + g;
#pragma unroll
        for (int nj = 0; nj < 4; nj++) {
            const int col = colBase + wn * 32 + nj * 8 + q2;
            const float bx = bias[col], by = bias[col + 1];
            float2 v0 = make_float2(c[mi][nj][0] + bx, c[mi][nj][1] + by);
            float2 v1 = make_float2(c[mi][nj][2] + bx, c[mi][nj][3] + by);
            *(float2*)(Cm + (size_t)row0 * N + col) = v0;
            *(float2*)(Cm + (size_t)(row0 + 8) * N + col) = v1;
        }
    }
}

// ---------------------------------------------------------------------------
// Flash attention with mma.sync bf16 split.
// CTA: 128 q-rows x all kv, 8 warps (16 q-rows each), k-tile 64.
// smem: Khi|Klo|Vhi|Vlo (8K each) + Qhi|Qlo (16K each) = 64KB dynamic.
// ---------------------------------------------------------------------------
#define SM_KHI 0
#define SM_KLO 8192
#define SM_VHI 16384
#define SM_VLO 24576
#define SM_QHI 32768
#define SM_QLO 49152
#define A_SMEM 65536

__global__ __launch_bounds__(256, 1)
void attn_mma_kernel(const float* __restrict__ qkv,
                     __nv_bfloat16* __restrict__ yhi, __nv_bfloat16* __restrict__ ylo)
{
    extern __shared__ char smem[];
    const uint32_t sb = smem_u32(smem);
    const int qt = (int)gridDim.x - 1 - (int)blockIdx.x;   // longest work first
    const int bh = blockIdx.y;
    const int b = bh / H_, h = bh % H_;
    const int tid = threadIdx.x, wid = tid >> 5, lane = tid & 31;
    const int qBase = qt * 128;
    const float* base = qkv + (size_t)b * T_ * QKVC_ + h * 64;

    // ---- load Q tile (scaled by 1/8), split into smem ----
    for (int idx = tid; idx < 128 * 16; idx += 256) {
        const int r = idx >> 4, c4 = (idx & 15) * 4;
        float4 v = *(const float4*)(base + (size_t)(qBase + r) * QKVC_ + c4);
        v.x *= 0.125f; v.y *= 0.125f; v.z *= 0.125f; v.w *= 0.125f;
        uint32_t h0, l0, h1, l1;
        split2(v.x, v.y, h0, l0);
        split2(v.z, v.w, h1, l1);
        const uint32_t off = SWZ((uint32_t)r * 128 + c4 * 2);
        *(uint32_t*)(smem + SM_QHI + off) = h0;
        *(uint32_t*)(smem + SM_QHI + off + 4) = h1;
        *(uint32_t*)(smem + SM_QLO + off) = l0;
        *(uint32_t*)(smem + SM_QLO + off + 4) = l1;
    }
    __syncthreads();

    // ---- Q fragments (register resident) ----
    uint32_t qh[4][4], ql[4][4];
    {
        const int aRow = wid * 16 + (lane & 15);
        const uint32_t aSeg = ((lane >> 4) & 1) * 16;
#pragma unroll
        for (int ks = 0; ks < 4; ks++) {
            const uint32_t aoff = SWZ((uint32_t)aRow * 128 + ks * 32 + aSeg);
            ldsm_x4(qh[ks][0], qh[ks][1], qh[ks][2], qh[ks][3], sb + SM_QHI + aoff);
            ldsm_x4(ql[ks][0], ql[ks][1], ql[ks][2], ql[ks][3], sb + SM_QLO + aoff);
        }
    }

    float o[8][4];
#pragma unroll
    for (int d = 0; d < 8; d++)
#pragma unroll
        for (int k = 0; k < 4; k++) o[d][k] = 0.f;
    float m0 = -1e30f, m1 = -1e30f, l0s = 0.f, l1s = 0.f;

    const int g = lane >> 2, q2 = (lane & 3) * 2;
    const int row0 = qBase + wid * 16 + g;     // row1 = row0 + 8
    const int rowWarpMax = qBase + wid * 16 + 15;
    const int ktMax = 2 * qt + 1;

    const int bRowL = lane & 7;
    const uint32_t bSeg = ((lane >> 3) & 1) * 16;
    const int vRowL = lane & 15;

    for (int kt = 0; kt <= ktMax; kt++) {
        const int kBase = kt * 64;
        __syncthreads();
        // ---- load K,V tiles, split into smem ----
        for (int idx = tid; idx < 64 * 16; idx += 256) {
            const int r = idx >> 4, c4 = (idx & 15) * 4;
            const size_t roff = (size_t)(kBase + r) * QKVC_ + c4;
            float4 kv = *(const float4*)(base + C_ + roff);
            float4 vv = *(const float4*)(base + 2 * C_ + roff);
            uint32_t h0, l0, h1, l1;
            const uint32_t off = SWZ((uint32_t)r * 128 + c4 * 2);
            split2(kv.x, kv.y, h0, l0); split2(kv.z, kv.w, h1, l1);
            *(uint32_t*)(smem + SM_KHI + off) = h0;
            *(uint32_t*)(smem + SM_KHI + off + 4) = h1;
            *(uint32_t*)(smem + SM_KLO + off) = l0;
            *(uint32_t*)(smem + SM_KLO + off + 4) = l1;
            split2(vv.x, vv.y, h0, l0); split2(vv.z, vv.w, h1, l1);
            *(uint32_t*)(smem + SM_VHI + off) = h0;
            *(uint32_t*)(smem + SM_VHI + off + 4) = h1;
            *(uint32_t*)(smem + SM_VLO + off) = l0;
            *(uint32_t*)(smem + SM_VLO + off + 4) = l1;
        }
        __syncthreads();

        if (kBase > rowWarpMax) continue;   // warp fully masked (uniform)

        // ---- S = Q K^T ----
        float sc[8][4];
#pragma unroll
        for (int nj = 0; nj < 8; nj++)
#pragma unroll
            for (int k = 0; k < 4; k++) sc[nj][k] = 0.f;
#pragma unroll
        for (int nj = 0; nj < 8; nj++) {
#pragma unroll
            for (int ks = 0; ks < 4; ks++) {
                const uint32_t boff = SWZ((uint32_t)(nj * 8 + bRowL) * 128 + ks * 32 + bSeg);
                uint32_t k0, k1;
                ldsm_x2(k0, k1, sb + SM_KHI + boff);
                mma_bf16(sc[nj], qh[ks], k0, k1);
                mma_bf16(sc[nj], ql[ks], k0, k1);
                ldsm_x2(k0, k1, sb + SM_KLO + boff);
                mma_bf16(sc[nj], qh[ks], k0, k1);
            }
        }

        // ---- causal mask (diagonal tiles only) ----
        if (kBase + 63 > qBase + wid * 16) {
#pragma unroll
            for (int nj = 0; nj < 8; nj++) {
                const int col = kBase + nj * 8 + q2;
                if (col > row0)     sc[nj][0] = -1e30f;
                if (col + 1 > row0) sc[nj][1] = -1e30f;
                if (col > row0 + 8)     sc[nj][2] = -1e30f;
                if (col + 1 > row0 + 8) sc[nj][3] = -1e30f;
            }
        }

        // ---- online softmax ----
        float mx0 = -1e30f, mx1 = -1e30f;
#pragma unroll
        for (int nj = 0; nj < 8; nj++) {
            mx0 = fmaxf(mx0, fmaxf(sc[nj][0], sc[nj][1]));
            mx1 = fmaxf(mx1, fmaxf(sc[nj][2], sc[nj][3]));
        }
        mx0 = fmaxf(mx0, __shfl_xor_sync(0xffffffffu, mx0, 1));
        mx0 = fmaxf(mx0, __shfl_xor_sync(0xffffffffu, mx0, 2));
        mx1 = fmaxf(mx1, __shfl_xor_sync(0xffffffffu, mx1, 1));
        mx1 = fmaxf(mx1, __shfl_xor_sync(0xffffffffu, mx1, 2));
        const float mn0 = fmaxf(m0, mx0), mn1 = fmaxf(m1, mx1);
        const float al0 = __expf(m0 - mn0), al1 = __expf(m1 - mn1);
        m0 = mn0; m1 = mn1;
        float s0 = 0.f, s1 = 0.f;
#pragma unroll
        for (int nj = 0; nj < 8; nj++) {
            sc[nj][0] = __expf(sc[nj][0] - mn0);
            sc[nj][1] = __expf(sc[nj][1] - mn0);
            sc[nj][2] = __expf(sc[nj][2] - mn1);
            sc[nj][3] = __expf(sc[nj][3] - mn1);
            s0 += sc[nj][0] + sc[nj][1];
            s1 += sc[nj][2] + sc[nj][3];
        }
        s0 += __shfl_xor_sync(0xffffffffu, s0, 1);
        s0 += __shfl_xor_sync(0xffffffffu, s0, 2);
        s1 += __shfl_xor_sync(0xffffffffu, s1, 1);
        s1 += __shfl_xor_sync(0xffffffffu, s1, 2);
        l0s = l0s * al0 + s0;
        l1s = l1s * al1 + s1;

        // ---- P fragments (register remap, split) ----
        uint32_t ph[4][4], pl[4][4];
#pragma unroll
        for (int ks = 0; ks < 4; ks++) {
            split2(sc[2 * ks][0],     sc[2 * ks][1],     ph[ks][0], pl[ks][0]);
            split2(sc[2 * ks][2],     sc[2 * ks][3],     ph[ks][1], pl[ks][1]);
            split2(sc[2 * ks + 1][0], sc[2 * ks + 1][1], ph[ks][2], pl[ks][2]);
            split2(sc[2 * ks + 1][2], sc[2 * ks + 1][3], ph[ks][3], pl[ks][3]);
        }

        // ---- rescale O, accumulate P V ----
#pragma unroll
        for (int dj = 0; dj < 8; dj++) {
            o[dj][0] *= al0; o[dj][1] *= al0;
            o[dj][2] *= al1; o[dj][3] *= al1;
#pragma unroll
            for (int ks = 0; ks < 4; ks++) {
                const uint32_t voff = SWZ((uint32_t)(ks * 16 + vRowL) * 128 + dj * 16);
                uint32_t v0, v1;
                ldsm_x2t(v0, v1, sb + SM_VHI + voff);
                mma_bf16(o[dj], ph[ks], v0, v1);
                mma_bf16(o[dj], pl[ks], v0, v1);
                ldsm_x2t(v0, v1, sb + SM_VLO + voff);
                mma_bf16(o[dj], ph[ks], v0, v1);
            }
        }
    }

    // ---- epilogue: O/l -> bf16 hi/lo ----
    const float inv0 = 1.0f / l0s, inv1 = 1.0f / l1s;
#pragma unroll
    for (int dj = 0; dj < 8; dj++) {
        uint32_t h0, l0, h1, l1;
        split2(o[dj][0] * inv0, o[dj][1] * inv0, h0, l0);
        split2(o[dj][2] * inv1, o[dj][3] * inv1, h1, l1);
        const size_t r0 = ((size_t)b * T_ + row0) * C_ + h * 64 + dj * 8 + q2;
        const size_t r1 = r0 + 8 * C_;
        *(uint32_t*)(yhi + r0) = h0;
        *(uint32_t*)(ylo + r0) = l0;
        *(uint32_t*)(yhi + r1) = h1;
        *(uint32_t*)(ylo + r1) = l1;
    }
}

// ---------------------------------------------------------------------------
extern "C" void kernel_launch(void* const* d_in, const int* in_sizes, int n_in,
                              void* d_out, int out_size)
{
    const float* x      = (const float*)d_in[0];
    const float* w_attn = (const float*)d_in[1];
    const float* b_attn = (const float*)d_in[2];
    const float* w_proj = (const float*)d_in[3];
    const float* b_proj = (const float*)d_in[4];
    float* out = (float*)d_out;

    float* qkv; __nv_bfloat16 *xhi, *xlo, *yhi, *ylo, *wah, *wal, *wph, *wpl;
    cudaGetSymbolAddress((void**)&qkv, g_qkv);
    cudaGetSymbolAddress((void**)&xhi, g_xhi);
    cudaGetSymbolAddress((void**)&xlo, g_xlo);
    cudaGetSymbolAddress((void**)&yhi, g_yhi);
    cudaGetSymbolAddress((void**)&ylo, g_ylo);
    cudaGetSymbolAddress((void**)&wah, g_wa_hi);
    cudaGetSymbolAddress((void**)&wal, g_wa_lo);
    cudaGetSymbolAddress((void**)&wph, g_wp_hi);
    cudaGetSymbolAddress((void**)&wpl, g_wp_lo);

    cudaFuncSetAttribute(gemm_mma_kernel,
                         cudaFuncAttributeMaxDynamicSharedMemorySize, G_SMEM);
    cudaFuncSetAttribute(attn_mma_kernel,
                         cudaFuncAttributeMaxDynamicSharedMemorySize, A_SMEM);

    // conversions
    {
        int n4 = ROWS_ * C_ / 4;
        split_rows_kernel<<<(n4 + 255) / 256, 256>>>(x, xhi, xlo, n4);
        dim3 bt(32, 8);
        split_transpose_kernel<<<dim3(QKVC_ / 32, C_ / 32), bt>>>(w_attn, wah, wal, C_, QKVC_);
        split_transpose_kernel<<<dim3(C_ / 32,    C_ / 32), bt>>>(w_proj, wph, wpl, C_, C_);
    }
    // Stage 1: qkv = x @ w_attn + b_attn   [8192 x 2304]
    {
        dim3 grid(QKVC_ / 128, ROWS_ / 128);
        gemm_mma_kernel<<<grid, 256, G_SMEM>>>(xhi, xlo, wah, wal, b_attn, qkv,
                                               ROWS_, QKVC_, C_);
    }
    // Stage 2: attention -> y (bf16 hi/lo)
    {
        dim3 grid(T_ / 128, B_ * H_);
        attn_mma_kernel<<<grid, 256, A_SMEM>>>(qkv, yhi, ylo);
    }
    // Stage 3: out = y @ w_proj + b_proj   [8192 x 768]
    {
        dim3 grid(C_ / 128, ROWS_ / 128);
        gemm_mma_kernel<<<grid, 256, G_SMEM>>>(yhi, ylo, wph, wpl, b_proj, out,
                                               ROWS_, C_, C_);
    }
}